// round 15
// baseline (speedup 1.0000x reference)
#include <cuda_runtime.h>
#include <math.h>
#include <stdint.h>

// MoE FFN: T=8192 tokens, D=1024, F=4096, E=8, top-2.
// Inputs: x[T,D] f32, W_gate[E,D] f32, Wg[E,F,D] f32, Wu[E,F,D] f32, Wd[E,D,F] f32.
// Output: [T,D] f32.
// mma.sync m16n8k8 tf32 + ldmatrix, single-barrier 3-stage cp.async pipeline.
// R15: no prepass — fragments cvt.rna.tf32 in-loop (bit-identical numerics);
//      3 pad kernels so ncu (-s 5) profiles ffn1_mma.

#define NT 8192
#define DD 1024
#define FF 4096
#define NE 8

#define BM 128
#define BN 128
#define BK 32
#define KSTRIDE 36          // smem row stride in floats (pad 32 -> 36)

// ---------------- scratch ----------------
__device__ int   g_count[NE];
__device__ int   g_pairs[NE][NT];   // pair = token*2 + k
__device__ float g_wts[NE][NT];
__device__ float g_h[(size_t)NT * 2 * FF];     // 256 MiB (tf32-rounded)
__device__ float g_o[(size_t)NT * 2 * DD];     // 64 MiB per-pair outputs

// ---------------- helpers ----------------
__device__ __forceinline__ uint32_t smem_u32(const void* p) {
    uint32_t a;
    asm("{ .reg .u64 t; cvta.to.shared.u64 t, %1; cvt.u32.u64 %0, t; }" : "=r"(a) : "l"(p));
    return a;
}
__device__ __forceinline__ float tf32r(float x) {
    uint32_t r; asm("cvt.rna.tf32.f32 %0, %1;" : "=r"(r) : "f"(x));
    return __uint_as_float(r);
}
__device__ __forceinline__ uint32_t tf32u(uint32_t x) {
    uint32_t r; asm("cvt.rna.tf32.f32 %0, %1;" : "=r"(r) : "f"(__uint_as_float(x)));
    return r;
}
#define CPA16(dst, src, sz) \
    asm volatile("cp.async.cg.shared.global [%0], [%1], 16, %2;" \
                 :: "r"(dst), "l"(src), "r"(sz) : "memory")
#define CP_COMMIT() asm volatile("cp.async.commit_group;" ::: "memory")
#define CP_WAIT1()  asm volatile("cp.async.wait_group 1;" ::: "memory")

#define MMA_TF32(d, a0, a1, a2, a3, b0, b1) \
    asm volatile("mma.sync.aligned.m16n8k8.row.col.f32.tf32.tf32.f32 " \
        "{%0,%1,%2,%3}, {%4,%5,%6,%7}, {%8,%9}, {%0,%1,%2,%3};" \
        : "+f"((d)[0]), "+f"((d)[1]), "+f"((d)[2]), "+f"((d)[3]) \
        : "r"(a0), "r"(a1), "r"(a2), "r"(a3), "r"(b0), "r"(b1))

#define LDSM4(r0, r1, r2, r3, addr) \
    asm volatile("ldmatrix.sync.aligned.m8n8.x4.shared.b16 {%0,%1,%2,%3}, [%4];" \
        : "=r"(r0), "=r"(r1), "=r"(r2), "=r"(r3) : "r"(addr))

// ---------------- router ----------------
__global__ void zero_counts_kernel() {
    if (threadIdx.x < NE) g_count[threadIdx.x] = 0;
}

// tiny pad kernels so ffn1_mma is the 6th launch (ncu -s 5 -c 1 profiles it)
__global__ void pad_kernel() {}

__global__ void router_kernel(const float* __restrict__ x,
                              const float* __restrict__ Wgate) {
    int warp = (blockIdx.x * blockDim.x + threadIdx.x) >> 5;
    int lane = threadIdx.x & 31;
    if (warp >= NT) return;
    const float* xr = x + (size_t)warp * DD;

    float lg[NE];
#pragma unroll
    for (int e = 0; e < NE; e++) {
        const float* w = Wgate + e * DD;
        float acc = 0.f;
#pragma unroll 8
        for (int i = lane; i < DD; i += 32) acc = fmaf(xr[i], w[i], acc);
#pragma unroll
        for (int o = 16; o; o >>= 1) acc += __shfl_xor_sync(0xffffffffu, acc, o);
        lg[e] = acc;
    }
    if (lane == 0) {
        int e0 = 0;
#pragma unroll
        for (int e = 1; e < NE; e++) if (lg[e] > lg[e0]) e0 = e;
        int e1 = (e0 == 0) ? 1 : 0;
#pragma unroll
        for (int e = 0; e < NE; e++) {
            if (e == e0 || e == e1) continue;
            if (lg[e] > lg[e1]) e1 = e;
        }
        float w0 = 1.f / (1.f + expf(lg[e1] - lg[e0]));
        float w1 = 1.f - w0;
        int p0 = atomicAdd(&g_count[e0], 1);
        g_pairs[e0][p0] = warp * 2;     g_wts[e0][p0] = w0;
        int p1 = atomicAdd(&g_count[e1], 1);
        g_pairs[e1][p1] = warp * 2 + 1; g_wts[e1][p1] = w1;
    }
}

// ---------------- GEMM1: gate+up fused ----------------
// dyn smem floats: stage s (0..2) at s*13824: A[128][36] @0, Bg @4608, Bu @9216
// sp[] at float offset 41472.  Bytes = 165888 + 512.
#define ST1 13824
#define SMEM1_BYTES (165888 + 512)

__global__ void __launch_bounds__(256, 1) ffn1_mma(const float* __restrict__ x,
                                                   const float* __restrict__ Wg,
                                                   const float* __restrict__ Wu) {
    const int e   = blockIdx.z;
    const int cnt = g_count[e];
    const int m0  = blockIdx.x * BM;
    if (m0 >= cnt) return;
    const int n0  = blockIdx.y * BN;

    extern __shared__ float S[];
    int* sp = (int*)(S + 41472);
    const uint32_t sb = smem_u32(S);
    const int tid = threadIdx.x;

    if (tid < BM) {
        int s = m0 + tid;
        sp[tid] = (s < cnt) ? g_pairs[e][s] : -1;
    }
    __syncthreads();

    const int r0 = tid >> 3;
    const int c4 = (tid & 7) * 4;
    const float* ap[4];
    uint32_t asz[4];
#pragma unroll
    for (int i = 0; i < 4; i++) {
        int p = sp[r0 + 32 * i];
        asz[i] = (p >= 0) ? 16u : 0u;
        ap[i] = x + (size_t)((p >= 0) ? (p >> 1) : 0) * DD + c4;
    }
    const float* wgb = Wg + (size_t)e * FF * DD + (size_t)(n0 + r0) * DD + c4;
    const float* wub = Wu + (size_t)e * FF * DD + (size_t)(n0 + r0) * DD + c4;
    const uint32_t rowb = (uint32_t)(r0 * KSTRIDE + c4) * 4u;

    const int lane = tid & 31;
    const int g  = lane >> 2;
    const int tg = lane & 3;
    const int wm = (tid >> 5) & 3;
    const int wn = tid >> 7;

    const int lt = lane >> 3;
    const int tr = lane & 7;
    uint32_t aoff[2];
#pragma unroll
    for (int i = 0; i < 2; i++) {
        int row = wm * 32 + i * 16 + (lt & 1) * 8 + tr;
        aoff[i] = (uint32_t)(row * KSTRIDE + (lt >> 1) * 4) * 4u;
    }
    uint32_t boff[4];
#pragma unroll
    for (int p = 0; p < 4; p++) {
        int row = wn * 64 + p * 16 + (lt >> 1) * 8 + tr;
        boff[p] = (uint32_t)(row * KSTRIDE + (lt & 1) * 4) * 4u;
    }

    float accg[2][8][4], accu[2][8][4];
#pragma unroll
    for (int i = 0; i < 2; i++)
#pragma unroll
        for (int j = 0; j < 8; j++)
#pragma unroll
            for (int q = 0; q < 4; q++) { accg[i][j][q] = 0.f; accu[i][j][q] = 0.f; }

    const int NC = DD / BK;   // 32

    auto fill = [&](int ch) {
        const uint32_t so = (uint32_t)(ch % 3) * ((uint32_t)ST1 * 4u);
        const int k0 = ch * BK;
        uint32_t sA = sb + so + rowb;
        uint32_t sG = sA + 4608u * 4u;
        uint32_t sU = sA + 9216u * 4u;
#pragma unroll
        for (int i = 0; i < 4; i++) {
            CPA16(sA + i * (32u * KSTRIDE * 4u), ap[i] + k0, asz[i]);
            CPA16(sG + i * (32u * KSTRIDE * 4u), wgb + (size_t)i * 32 * DD + k0, 16u);
            CPA16(sU + i * (32u * KSTRIDE * 4u), wub + (size_t)i * 32 * DD + k0, 16u);
        }
    };

    fill(0); CP_COMMIT();
    fill(1); CP_COMMIT();

    for (int c = 0; c < NC; c++) {
        CP_WAIT1();           // stage c resident
        __syncthreads();      // single barrier per chunk

        const uint32_t stg = sb + (uint32_t)(c % 3) * ((uint32_t)ST1 * 4u);
        const uint32_t sG  = stg + 4608u * 4u;
        const uint32_t sU  = stg + 9216u * 4u;

#pragma unroll
        for (int s = 0; s < 4; s++) {
            const uint32_t kb = (uint32_t)s * 32u;
            uint32_t af[2][4];
            LDSM4(af[0][0], af[0][1], af[0][2], af[0][3], stg + aoff[0] + kb);
            LDSM4(af[1][0], af[1][1], af[1][2], af[1][3], stg + aoff[1] + kb);
#pragma unroll
            for (int i = 0; i < 2; i++)
#pragma unroll
                for (int q = 0; q < 4; q++) af[i][q] = tf32u(af[i][q]);
#pragma unroll
            for (int p = 0; p < 4; p++) {
                uint32_t bg0, bg1, bg2, bg3, bu0, bu1, bu2, bu3;
                LDSM4(bg0, bg1, bg2, bg3, sG + boff[p] + kb);
                LDSM4(bu0, bu1, bu2, bu3, sU + boff[p] + kb);
                bg0 = tf32u(bg0); bg1 = tf32u(bg1); bg2 = tf32u(bg2); bg3 = tf32u(bg3);
                bu0 = tf32u(bu0); bu1 = tf32u(bu1); bu2 = tf32u(bu2); bu3 = tf32u(bu3);
                const int j0 = p * 2, j1 = p * 2 + 1;
                MMA_TF32(accg[0][j0], af[0][0], af[0][1], af[0][2], af[0][3], bg0, bg1);
                MMA_TF32(accg[1][j0], af[1][0], af[1][1], af[1][2], af[1][3], bg0, bg1);
                MMA_TF32(accg[0][j1], af[0][0], af[0][1], af[0][2], af[0][3], bg2, bg3);
                MMA_TF32(accg[1][j1], af[1][0], af[1][1], af[1][2], af[1][3], bg2, bg3);
                MMA_TF32(accu[0][j0], af[0][0], af[0][1], af[0][2], af[0][3], bu0, bu1);
                MMA_TF32(accu[1][j0], af[1][0], af[1][1], af[1][2], af[1][3], bu0, bu1);
                MMA_TF32(accu[0][j1], af[0][0], af[0][1], af[0][2], af[0][3], bu2, bu3);
                MMA_TF32(accu[1][j1], af[1][0], af[1][1], af[1][2], af[1][3], bu2, bu3);
            }
        }

        // fill stage (c+2)%3 AFTER compute: safe vs laggards with 3 stages
        if (c + 2 < NC) fill(c + 2);
        CP_COMMIT();
    }

    // epilogue: h = tf32_round(silu(gate)*up) -> g_h[pair][col]
#pragma unroll
    for (int i = 0; i < 2; i++) {
#pragma unroll
        for (int half = 0; half < 2; half++) {
            const int rl = wm * 32 + i * 16 + g + half * 8;
            const int pr = sp[rl];
            if (pr < 0) continue;
            float* hrow = g_h + (size_t)pr * FF + n0 + wn * 64 + 2 * tg;
#pragma unroll
            for (int j = 0; j < 8; j++) {
                float gv0 = accg[i][j][half * 2 + 0];
                float gv1 = accg[i][j][half * 2 + 1];
                float2 hv;
                hv.x = tf32r(gv0 / (1.f + expf(-gv0)) * accu[i][j][half * 2 + 0]);
                hv.y = tf32r(gv1 / (1.f + expf(-gv1)) * accu[i][j][half * 2 + 1]);
                *(float2*)(hrow + j * 8) = hv;
            }
        }
    }
}

// ---------------- GEMM2: down proj ----------------
// dyn smem floats: stage s (0..2) at s*9216: A[128][36] @0, B @4608
// sp at float 27648, sw at 27776. Bytes = 110592 + 1024.
#define ST2 9216
#define SMEM2_BYTES (110592 + 1024)

__global__ void __launch_bounds__(256, 2) ffn2_mma(const float* __restrict__ Wd) {
    const int e   = blockIdx.z;
    const int cnt = g_count[e];
    const int m0  = blockIdx.x * BM;
    if (m0 >= cnt) return;
    const int n0  = blockIdx.y * BN;   // over D

    extern __shared__ float S[];
    int*   sp = (int*)(S + 27648);
    float* sw = S + 27776;
    const uint32_t sb = smem_u32(S);
    const int tid = threadIdx.x;

    if (tid < BM) {
        int s = m0 + tid;
        sp[tid] = (s < cnt) ? g_pairs[e][s] : -1;
        sw[tid] = (s < cnt) ? g_wts[e][s] : 0.f;
    }
    __syncthreads();

    const int r0 = tid >> 3;
    const int c4 = (tid & 7) * 4;
    const float* ap[4];
    uint32_t asz[4];
#pragma unroll
    for (int i = 0; i < 4; i++) {
        int p = sp[r0 + 32 * i];
        asz[i] = (p >= 0) ? 16u : 0u;
        ap[i] = g_h + (size_t)((p >= 0) ? p : 0) * FF + c4;
    }
    const float* wb = Wd + (size_t)e * DD * FF + (size_t)(n0 + r0) * FF + c4;
    const uint32_t rowb = (uint32_t)(r0 * KSTRIDE + c4) * 4u;

    const int lane = tid & 31;
    const int g  = lane >> 2;
    const int tg = lane & 3;
    const int wm = (tid >> 5) & 3;
    const int wn = tid >> 7;

    const int lt = lane >> 3;
    const int tr = lane & 7;
    uint32_t aoff[2];
#pragma unroll
    for (int i = 0; i < 2; i++) {
        int row = wm * 32 + i * 16 + (lt & 1) * 8 + tr;
        aoff[i] = (uint32_t)(row * KSTRIDE + (lt >> 1) * 4) * 4u;
    }
    uint32_t boff[4];
#pragma unroll
    for (int p = 0; p < 4; p++) {
        int row = wn * 64 + p * 16 + (lt >> 1) * 8 + tr;
        boff[p] = (uint32_t)(row * KSTRIDE + (lt & 1) * 4) * 4u;
    }

    float acc[2][8][4];
#pragma unroll
    for (int i = 0; i < 2; i++)
#pragma unroll
        for (int j = 0; j < 8; j++)
#pragma unroll
            for (int q = 0; q < 4; q++) acc[i][j][q] = 0.f;

    const int NC = FF / BK;   // 128

    auto fill = [&](int ch) {
        const uint32_t so = (uint32_t)(ch % 3) * ((uint32_t)ST2 * 4u);
        const int k0 = ch * BK;
        uint32_t sA = sb + so + rowb;
        uint32_t sB = sA + 4608u * 4u;
#pragma unroll
        for (int i = 0; i < 4; i++) {
            CPA16(sA + i * (32u * KSTRIDE * 4u), ap[i] + k0, asz[i]);
            CPA16(sB + i * (32u * KSTRIDE * 4u), wb + (size_t)i * 32 * FF + k0, 16u);
        }
    };

    fill(0); CP_COMMIT();
    fill(1); CP_COMMIT();

    for (int c = 0; c < NC; c++) {
        CP_WAIT1();
        __syncthreads();

        const uint32_t stg = sb + (uint32_t)(c % 3) * ((uint32_t)ST2 * 4u);
        const uint32_t sB  = stg + 4608u * 4u;

#pragma unroll
        for (int s = 0; s < 4; s++) {
            const uint32_t kb = (uint32_t)s * 32u;
            uint32_t af[2][4];
            LDSM4(af[0][0], af[0][1], af[0][2], af[0][3], stg + aoff[0] + kb);
            LDSM4(af[1][0], af[1][1], af[1][2], af[1][3], stg + aoff[1] + kb);
            // A (g_h) is already tf32-rounded by ffn1's epilogue; no cvt.
#pragma unroll
            for (int p = 0; p < 4; p++) {
                uint32_t b0, b1, b2, b3;
                LDSM4(b0, b1, b2, b3, sB + boff[p] + kb);
                b0 = tf32u(b0); b1 = tf32u(b1); b2 = tf32u(b2); b3 = tf32u(b3);
                const int j0 = p * 2, j1 = p * 2 + 1;
                MMA_TF32(acc[0][j0], af[0][0], af[0][1], af[0][2], af[0][3], b0, b1);
                MMA_TF32(acc[1][j0], af[1][0], af[1][1], af[1][2], af[1][3], b0, b1);
                MMA_TF32(acc[0][j1], af[0][0], af[0][1], af[0][2], af[0][3], b2, b3);
                MMA_TF32(acc[1][j1], af[1][0], af[1][1], af[1][2], af[1][3], b2, b3);
            }
        }

        if (c + 2 < NC) fill(c + 2);
        CP_COMMIT();
    }

    // epilogue: g_o[pair] = acc * w  (plain stores; combine kernel sums)
#pragma unroll
    for (int i = 0; i < 2; i++) {
#pragma unroll
        for (int half = 0; half < 2; half++) {
            const int rl = wm * 32 + i * 16 + g + half * 8;
            const int pr = sp[rl];
            if (pr < 0) continue;
            const float w = sw[rl];
            float* orow = g_o + (size_t)pr * DD + n0 + wn * 64 + 2 * tg;
#pragma unroll
            for (int j = 0; j < 8; j++) {
                float2 ov;
                ov.x = acc[i][j][half * 2 + 0] * w;
                ov.y = acc[i][j][half * 2 + 1] * w;
                *(float2*)(orow + j * 8) = ov;
            }
        }
    }
}

// ---------------- combine: out[t] = g_o[2t] + g_o[2t+1] ----------------
__global__ void combine_kernel(float4* __restrict__ out) {
    int i = blockIdx.x * blockDim.x + threadIdx.x;
    if (i >= NT * DD / 4) return;
    const int t  = i / (DD / 4);
    const int d4 = i % (DD / 4);
    const float4* a = (const float4*)(g_o + (size_t)(2 * t) * DD) + d4;
    const float4* b = (const float4*)(g_o + (size_t)(2 * t + 1) * DD) + d4;
    float4 va = *a, vb = *b;
    va.x += vb.x; va.y += vb.y; va.z += vb.z; va.w += vb.w;
    out[i] = va;
}

// ---------------------------------------------------------------------------
extern "C" void kernel_launch(void* const* d_in, const int* in_sizes, int n_in,
                              void* d_out, int out_size) {
    const float* x     = (const float*)d_in[0];
    const float* Wgate = (const float*)d_in[1];
    const float* Wg    = (const float*)d_in[2];
    const float* Wu    = (const float*)d_in[3];
    const float* Wd    = (const float*)d_in[4];
    float* out = (float*)d_out;

    cudaFuncSetAttribute(ffn1_mma, cudaFuncAttributeMaxDynamicSharedMemorySize, SMEM1_BYTES);
    cudaFuncSetAttribute(ffn2_mma, cudaFuncAttributeMaxDynamicSharedMemorySize, SMEM2_BYTES);

    // Launch order: ffn1_mma is the 6th launch so ncu (-s 5 -c 1) profiles it.
    zero_counts_kernel<<<1, 32>>>();                                  // 1
    router_kernel<<<NT / 8, 256>>>(x, Wgate);                         // 2
    pad_kernel<<<1, 32>>>();                                          // 3
    pad_kernel<<<1, 32>>>();                                          // 4
    pad_kernel<<<1, 32>>>();                                          // 5

    dim3 g1(NT / BM, FF / BN, NE);
    ffn1_mma<<<g1, 256, SMEM1_BYTES>>>(x, Wg, Wu);                    // 6

    dim3 g2(NT / BM, DD / BN, NE);
    ffn2_mma<<<g2, 256, SMEM2_BYTES>>>(Wd);                           // 7

    combine_kernel<<<(NT * DD / 4 + 255) / 256, 256>>>((float4*)out); // 8
}